// round 14
// baseline (speedup 1.0000x reference)
#include <cuda_runtime.h>
#include <math.h>
#include <float.h>
#include <stdint.h>

#define NN   20000
#define EE   340000
#define DD   128
#define CC1  256
#define SCHUNKS 148   // fused s1+atb chunks: 1 block/SM
#define SCANB 20      // ceil(NN/1024)
#define GTHREADS (148*1024)

// ---- output layout (element offsets into float* d_out) ----
#define OFF_S1  0
#define OFF_S2  (NN*CC1)
#define OFF_A1  (OFF_S2 + 256*32)
#define OFF_E3  (OFF_A1 + 32)
#define OFF_X1  (OFF_E3 + NN*DD)
#define OFF_X2  (OFF_X1 + 256*128)
#define OFF_E0  (OFF_X2 + 32*128)

// ---- scratch ----
__device__ float g_zf[NN*DD];
__device__ float g_m2[NN*DD];
__device__ float g_magg[NN*DD];
__device__ float g_asrc[NN];
__device__ float g_adst[NN];
__device__ int   g_deg[NN];
__device__ int   g_off[NN+1];
__device__ int   g_cur[NN];
__device__ int   g_csrc[EE];
__device__ float g_Wcomb[DD*CC1];        // 128x256
__device__ float g_bcomb[CC1];
__device__ float g_us[DD];
__device__ float g_ud[DD];
__device__ float g_cs[2];
__device__ float g_part[SCHUNKS*CC1*DD]; // per-chunk T partials (19.4MB)
__device__ float g_colsum[CC1];
__device__ float g_sumT[DD];
__device__ unsigned g_cnt;               // grid barrier (zero-init; self-resetting)
__device__ unsigned g_gen;               // generation (monotonic across replays)

// ---- persistent side stream + events ----
struct SideRes {
    cudaStream_t s;
    cudaEvent_t fork, join;
    SideRes() {
        cudaStreamCreateWithFlags(&s, cudaStreamNonBlocking);
        cudaEventCreateWithFlags(&fork, cudaEventDisableTiming);
        cudaEventCreateWithFlags(&join, cudaEventDisableTiming);
    }
};
static SideRes g_sr;

// ---- tf32 helpers ----
__device__ __forceinline__ float to_tf32(float x) {
    float r;
    asm("cvt.rna.tf32.f32 %0, %1;" : "=f"(r) : "f"(x));
    return r;
}
__device__ __forceinline__ void mma_tf32(float c[4],
    uint32_t a0, uint32_t a1, uint32_t a2, uint32_t a3,
    uint32_t b0, uint32_t b1)
{
    asm volatile(
        "mma.sync.aligned.m16n8k8.row.col.f32.tf32.tf32.f32 "
        "{%0,%1,%2,%3},{%4,%5,%6,%7},{%8,%9},{%0,%1,%2,%3};\n"
        : "+f"(c[0]), "+f"(c[1]), "+f"(c[2]), "+f"(c[3])
        : "r"(a0), "r"(a1), "r"(a2), "r"(a3), "r"(b0), "r"(b1));
}
__device__ __forceinline__ uint32_t fbits(float x) { return __float_as_uint(x); }

// ---- replay-safe grid barrier (148 blocks, all co-resident) ----
__device__ __forceinline__ void gbar() {
    __syncthreads();
    if (threadIdx.x == 0) {
        __threadfence();
        unsigned my_gen = *((volatile unsigned*)&g_gen);
        unsigned old = atomicAdd(&g_cnt, 1u);
        if (old == gridDim.x - 1) {
            g_cnt = 0;
            __threadfence();
            atomicAdd(&g_gen, 1u);
        } else {
            while (*((volatile unsigned*)&g_gen) == my_gen) { __nanosleep(64); }
        }
    }
    __syncthreads();
}

// ============================ persistent graph build ============================
// phases: zero deg -> count -> scan (blocks 0..19) -> fill
__global__ __launch_bounds__(1024, 1) void k_graph(
    const int* __restrict__ src, const int* __restrict__ dst)
{
    int g = blockIdx.x*1024 + threadIdx.x;

    // phase 0: zero degree counters
    for (int i = g; i < NN; i += GTHREADS) g_deg[i] = 0;
    gbar();

    // phase 1: count
    for (int e = g; e < EE; e += GTHREADS) atomicAdd(&g_deg[dst[e]], 1);
    gbar();

    // phase 2: scan (blocks 0..SCANB-1 run the proven scanall body)
    if (blockIdx.x < SCANB) {
        __shared__ int sh[1024];
        int t = threadIdx.x, b = blockIdx.x;
        int base = 0;
        for (int i = t; i < b*1024; i += 1024) base += g_deg[i];
        sh[t] = base; __syncthreads();
        #pragma unroll
        for (int st = 512; st > 0; st >>= 1) {
            if (t < st) sh[t] += sh[t+st];
            __syncthreads();
        }
        base = sh[0];
        __syncthreads();
        int i = b*1024 + t;
        int d = (i < NN) ? g_deg[i] : 0;
        sh[t] = d; __syncthreads();
        #pragma unroll
        for (int off = 1; off < 1024; off <<= 1) {
            int v = (t >= off) ? sh[t-off] : 0;
            __syncthreads();
            sh[t] += v;
            __syncthreads();
        }
        int excl = base + sh[t] - d;
        if (i < NN) { g_off[i] = excl; g_cur[i] = excl; }
        if (i == 0) g_off[NN] = EE;
    }
    gbar();

    // phase 3: fill
    for (int e = g; e < EE; e += GTHREADS) {
        int p = atomicAdd(&g_cur[dst[e]], 1);
        g_csrc[p] = src[e];
    }
}

// ============================ zf GEMM (split-TF32) + fold (merged) ============================
// blocks [0,157): zf tiles; blocks [157, 157+129): fold work (b2 = blockIdx-157)
#define ZF_BLOCKS 157
__global__ __launch_bounds__(256) void k_gemm_zf_fold(
    const float* __restrict__ A, const float* __restrict__ B,
    const float* __restrict__ bias, float* __restrict__ C,
    const float* __restrict__ We1, const float* __restrict__ be1,
    const float* __restrict__ Wa1, const float* __restrict__ ba1,
    const float* __restrict__ attW)
{
    extern __shared__ float zs[];
    int tid = threadIdx.x;

    if (blockIdx.x >= ZF_BLOCKS) {
        // ---------------- fold part ----------------
        int b = blockIdx.x - ZF_BLOCKS, t = tid;
        if (b < 128) {
            float* sWe = zs;
            if (t < 128) sWe[t] = We1[b*128 + t];
            __syncthreads();
            float acc = 0.f;
            #pragma unroll 8
            for (int k = 0; k < 128; k++) acc = fmaf(sWe[k], Wa1[k*256 + t], acc);
            g_Wcomb[b*256 + t] = acc;
        } else {
            float* ts = zs;           // 128
            float* td = zs + 128;     // 128
            float* bc = zs + 256;     // 256
            g_colsum[t] = 0.f;
            if (t < 128) g_sumT[t] = 0.f;
            if (t < 128) {
                float s1v = 0.f, s2v = 0.f;
                for (int c = 0; c < 256; c++) {
                    float w = Wa1[t*256 + c];
                    s1v = fmaf(w, attW[c], s1v);
                    s2v = fmaf(w, attW[256 + c], s2v);
                }
                ts[t] = s1v; td[t] = s2v;
            }
            {
                float s = 0.f;
                for (int e = 0; e < 128; e++) s = fmaf(be1[e], Wa1[e*256 + t], s);
                bc[t] = s + ba1[t];
                g_bcomb[t] = bc[t];
            }
            __syncthreads();
            if (t < 128) {
                float u1 = 0.f, u2 = 0.f;
                for (int e = 0; e < 128; e++) {
                    float w = We1[t*128 + e];
                    u1 = fmaf(w, ts[e], u1);
                    u2 = fmaf(w, td[e], u2);
                }
                g_us[t] = u1; g_ud[t] = u2;
            }
            if (t == 0) {
                float c1v = 0.f, c2v = 0.f;
                for (int c = 0; c < 256; c++) {
                    c1v = fmaf(bc[c], attW[c], c1v);
                    c2v = fmaf(bc[c], attW[256 + c], c2v);
                }
                g_cs[0] = c1v; g_cs[1] = c2v;
            }
        }
        return;
    }

    // ---------------- zf GEMM part ----------------
    float* Ahi = zs;
    float* Alo = Ahi + 128*36;
    float* Bhi = Alo + 128*36;
    float* Blo = Bhi + 32*136;

    int w = tid >> 5, lane = tid & 31;
    int gid = lane >> 2, tid4 = lane & 3;
    int msub = (w >> 1) * 32, nsub = (w & 1) * 64;
    int row0 = blockIdx.x * 128;

    float acc[2][8][4];
    #pragma unroll
    for (int mf = 0; mf < 2; mf++)
        #pragma unroll
        for (int nf = 0; nf < 8; nf++)
            #pragma unroll
            for (int q = 0; q < 4; q++) acc[mf][nf][q] = 0.f;

    for (int k0 = 0; k0 < 128; k0 += 32) {
        {
            int r = tid >> 1, cs = (tid & 1) * 16;
            int gr = row0 + r;
            #pragma unroll
            for (int i = 0; i < 4; i++) {
                float4 v = make_float4(0.f,0.f,0.f,0.f);
                if (gr < NN) v = *(const float4*)(A + (size_t)gr*128 + k0 + cs + i*4);
                float hx = to_tf32(v.x), hy = to_tf32(v.y), hz = to_tf32(v.z), hw = to_tf32(v.w);
                Ahi[r*36+cs+i*4+0] = hx; Alo[r*36+cs+i*4+0] = to_tf32(v.x - hx);
                Ahi[r*36+cs+i*4+1] = hy; Alo[r*36+cs+i*4+1] = to_tf32(v.y - hy);
                Ahi[r*36+cs+i*4+2] = hz; Alo[r*36+cs+i*4+2] = to_tf32(v.z - hz);
                Ahi[r*36+cs+i*4+3] = hw; Alo[r*36+cs+i*4+3] = to_tf32(v.w - hw);
            }
        }
        {
            int r = tid >> 3, cs = (tid & 7) * 16;
            #pragma unroll
            for (int i = 0; i < 4; i++) {
                float4 v = *(const float4*)(B + (size_t)(k0+r)*128 + cs + i*4);
                float hx = to_tf32(v.x), hy = to_tf32(v.y), hz = to_tf32(v.z), hw = to_tf32(v.w);
                Bhi[r*136+cs+i*4+0] = hx; Blo[r*136+cs+i*4+0] = to_tf32(v.x - hx);
                Bhi[r*136+cs+i*4+1] = hy; Blo[r*136+cs+i*4+1] = to_tf32(v.y - hy);
                Bhi[r*136+cs+i*4+2] = hz; Blo[r*136+cs+i*4+2] = to_tf32(v.z - hz);
                Bhi[r*136+cs+i*4+3] = hw; Blo[r*136+cs+i*4+3] = to_tf32(v.w - hw);
            }
        }
        __syncthreads();
        #pragma unroll
        for (int kk = 0; kk < 4; kk++) {
            int kb = kk*8;
            uint32_t ah[2][4], al[2][4];
            #pragma unroll
            for (int mf = 0; mf < 2; mf++) {
                int m = msub + mf*16 + gid;
                ah[mf][0] = fbits(Ahi[m*36     + kb + tid4    ]);
                ah[mf][1] = fbits(Ahi[(m+8)*36 + kb + tid4    ]);
                ah[mf][2] = fbits(Ahi[m*36     + kb + tid4 + 4]);
                ah[mf][3] = fbits(Ahi[(m+8)*36 + kb + tid4 + 4]);
                al[mf][0] = fbits(Alo[m*36     + kb + tid4    ]);
                al[mf][1] = fbits(Alo[(m+8)*36 + kb + tid4    ]);
                al[mf][2] = fbits(Alo[m*36     + kb + tid4 + 4]);
                al[mf][3] = fbits(Alo[(m+8)*36 + kb + tid4 + 4]);
            }
            #pragma unroll
            for (int nf = 0; nf < 8; nf++) {
                int c = nsub + nf*8 + gid;
                uint32_t bh0 = fbits(Bhi[(kb+tid4)*136 + c]);
                uint32_t bh1 = fbits(Bhi[(kb+tid4+4)*136 + c]);
                uint32_t bl0 = fbits(Blo[(kb+tid4)*136 + c]);
                uint32_t bl1 = fbits(Blo[(kb+tid4+4)*136 + c]);
                #pragma unroll
                for (int mf = 0; mf < 2; mf++) {
                    mma_tf32(acc[mf][nf], ah[mf][0], ah[mf][1], ah[mf][2], ah[mf][3], bh0, bh1);
                    mma_tf32(acc[mf][nf], ah[mf][0], ah[mf][1], ah[mf][2], ah[mf][3], bl0, bl1);
                    mma_tf32(acc[mf][nf], al[mf][0], al[mf][1], al[mf][2], al[mf][3], bh0, bh1);
                }
            }
        }
        __syncthreads();
    }
    #pragma unroll
    for (int mf = 0; mf < 2; mf++) {
        int rlo = row0 + msub + mf*16 + gid;
        int rhi = rlo + 8;
        #pragma unroll
        for (int nf = 0; nf < 8; nf++) {
            int c0 = nsub + nf*8 + 2*tid4;
            float b0v = bias[c0], b1v = bias[c0+1];
            if (rlo < NN) {
                float2 o; o.x = acc[mf][nf][0]+b0v; o.y = acc[mf][nf][1]+b1v;
                *(float2*)(C + (size_t)rlo*128 + c0) = o;
            }
            if (rhi < NN) {
                float2 o; o.x = acc[mf][nf][2]+b0v; o.y = acc[mf][nf][3]+b1v;
                *(float2*)(C + (size_t)rhi*128 + c0) = o;
            }
        }
    }
}

// ============================ segment mean (4 nodes/warp, fp32, cached loads) ============================
template<bool NORM, bool DOTS>
__global__ __launch_bounds__(256) void k_segmean(
    const float* __restrict__ zin, float* __restrict__ out)
{
    int warp = threadIdx.x >> 5, lane = threadIdx.x & 31;
    int node0 = (blockIdx.x*8 + warp) * 4;
    if (node0 >= NN) return;
    int offv = 0;
    if (lane < 5) offv = g_off[min(node0 + lane, NN)];
    const float* zl = zin + lane*4;
    float4 us4, ud4;
    if (DOTS) {
        us4 = *(const float4*)(g_us + lane*4);
        ud4 = *(const float4*)(g_ud + lane*4);
    }

    #pragma unroll
    for (int ni = 0; ni < 4; ni++) {
        int node = node0 + ni;
        if (node >= NN) break;
        int e0 = __shfl_sync(0xffffffffu, offv, ni);
        int e1 = __shfl_sync(0xffffffffu, offv, ni+1);
        float4 acc = make_float4(0.f,0.f,0.f,0.f);
        for (int base = e0; base < e1; base += 32) {
            int j = base + lane;
            int myidx = (j < e1) ? g_csrc[j] : 0;
            int cnt = min(32, e1 - base);
            int t = 0;
            for (; t + 4 <= cnt; t += 4) {
                int s0 = __shfl_sync(0xffffffffu, myidx, t);
                int s1i = __shfl_sync(0xffffffffu, myidx, t+1);
                int s2 = __shfl_sync(0xffffffffu, myidx, t+2);
                int s3 = __shfl_sync(0xffffffffu, myidx, t+3);
                float4 v0 = *(const float4*)(zl + (size_t)s0*DD);
                float4 v1 = *(const float4*)(zl + (size_t)s1i*DD);
                float4 v2 = *(const float4*)(zl + (size_t)s2*DD);
                float4 v3 = *(const float4*)(zl + (size_t)s3*DD);
                acc.x += (v0.x+v1.x) + (v2.x+v3.x);
                acc.y += (v0.y+v1.y) + (v2.y+v3.y);
                acc.z += (v0.z+v1.z) + (v2.z+v3.z);
                acc.w += (v0.w+v1.w) + (v2.w+v3.w);
            }
            for (; t < cnt; t++) {
                int sb = __shfl_sync(0xffffffffu, myidx, t);
                float4 v = *(const float4*)(zl + (size_t)sb*DD);
                acc.x += v.x; acc.y += v.y; acc.z += v.z; acc.w += v.w;
            }
        }
        float inv = 1.0f / (float)(e1 - e0);
        acc.x *= inv; acc.y *= inv; acc.z *= inv; acc.w *= inv;
        if (NORM) {
            float ss = acc.x*acc.x + acc.y*acc.y + acc.z*acc.z + acc.w*acc.w;
            #pragma unroll
            for (int o = 16; o > 0; o >>= 1) ss += __shfl_xor_sync(0xffffffffu, ss, o);
            float r = 1.0f / fmaxf(sqrtf(ss), 1e-12f);
            acc.x *= r; acc.y *= r; acc.z *= r; acc.w *= r;
        }
        *(float4*)(out + (size_t)node*DD + lane*4) = acc;
        if (DOTS) {
            float as = acc.x*us4.x + acc.y*us4.y + acc.z*us4.z + acc.w*us4.w;
            float ad = acc.x*ud4.x + acc.y*ud4.y + acc.z*ud4.z + acc.w*ud4.w;
            #pragma unroll
            for (int o = 16; o > 0; o >>= 1) {
                as += __shfl_xor_sync(0xffffffffu, as, o);
                ad += __shfl_xor_sync(0xffffffffu, ad, o);
            }
            if (lane == 0) { g_asrc[node] = as + g_cs[0]; g_adst[node] = ad + g_cs[1]; }
        }
    }
}

// ============================ GAT aggregation (4 nodes/warp, fp32, cached loads) ============================
__global__ __launch_bounds__(256) void k_gatagg(const float* __restrict__ attb)
{
    int warp = threadIdx.x >> 5, lane = threadIdx.x & 31;
    int node0 = (blockIdx.x*8 + warp) * 4;
    if (node0 >= NN) return;
    int offv = 0;
    if (lane < 5) offv = g_off[min(node0 + lane, NN)];
    float adv = 0.f;
    if (lane < 4) adv = g_adst[min(node0 + lane, NN-1)];
    float attb0 = attb[0];
    const float* zl = g_m2 + lane*4;

    #pragma unroll
    for (int ni = 0; ni < 4; ni++) {
        int node = node0 + ni;
        if (node >= NN) break;
        int e0 = __shfl_sync(0xffffffffu, offv, ni);
        int e1 = __shfl_sync(0xffffffffu, offv, ni+1);
        float adb = __shfl_sync(0xffffffffu, adv, ni) + attb0;

        float mx = -FLT_MAX;
        for (int j = e0 + lane; j < e1; j += 32) {
            float e = g_asrc[g_csrc[j]] + adb;
            e = (e > 0.f) ? e : 0.01f*e;
            mx = fmaxf(mx, e);
        }
        #pragma unroll
        for (int o = 16; o > 0; o >>= 1) mx = fmaxf(mx, __shfl_xor_sync(0xffffffffu, mx, o));

        float4 acc = make_float4(0.f,0.f,0.f,0.f);
        float denom = 0.f;
        for (int base = e0; base < e1; base += 32) {
            int j = base + lane;
            int s = 0; float a = 0.f;
            if (j < e1) {
                s = g_csrc[j];
                float e = g_asrc[s] + adb;
                e = (e > 0.f) ? e : 0.01f*e;
                a = __expf(e - mx);
                denom += a;
            }
            int cnt = min(32, e1 - base);
            int t = 0;
            for (; t + 4 <= cnt; t += 4) {
                float a0 = __shfl_sync(0xffffffffu, a, t);
                float a1 = __shfl_sync(0xffffffffu, a, t+1);
                float a2 = __shfl_sync(0xffffffffu, a, t+2);
                float a3 = __shfl_sync(0xffffffffu, a, t+3);
                int   s0 = __shfl_sync(0xffffffffu, s, t);
                int   s1i = __shfl_sync(0xffffffffu, s, t+1);
                int   s2 = __shfl_sync(0xffffffffu, s, t+2);
                int   s3 = __shfl_sync(0xffffffffu, s, t+3);
                float4 v0 = *(const float4*)(zl + (size_t)s0*DD);
                float4 v1 = *(const float4*)(zl + (size_t)s1i*DD);
                float4 v2 = *(const float4*)(zl + (size_t)s2*DD);
                float4 v3 = *(const float4*)(zl + (size_t)s3*DD);
                acc.x = fmaf(a0, v0.x, fmaf(a1, v1.x, fmaf(a2, v2.x, fmaf(a3, v3.x, acc.x))));
                acc.y = fmaf(a0, v0.y, fmaf(a1, v1.y, fmaf(a2, v2.y, fmaf(a3, v3.y, acc.y))));
                acc.z = fmaf(a0, v0.z, fmaf(a1, v1.z, fmaf(a2, v2.z, fmaf(a3, v3.z, acc.z))));
                acc.w = fmaf(a0, v0.w, fmaf(a1, v1.w, fmaf(a2, v2.w, fmaf(a3, v3.w, acc.w))));
            }
            for (; t < cnt; t++) {
                float ab = __shfl_sync(0xffffffffu, a, t);
                int   sb = __shfl_sync(0xffffffffu, s, t);
                float4 v = *(const float4*)(zl + (size_t)sb*DD);
                acc.x = fmaf(ab, v.x, acc.x); acc.y = fmaf(ab, v.y, acc.y);
                acc.z = fmaf(ab, v.z, acc.z); acc.w = fmaf(ab, v.w, acc.w);
            }
        }
        #pragma unroll
        for (int o = 16; o > 0; o >>= 1) denom += __shfl_xor_sync(0xffffffffu, denom, o);
        float r = 1.0f / denom;
        acc.x *= r; acc.y *= r; acc.z *= r; acc.w *= r;
        *(float4*)(g_magg + (size_t)node*DD + lane*4) = acc;
    }
}

// ============================ FUSED: s1 softmax GEMM + T partials + sumT/colsum ============================
#define S1ATB_SMEM_FLOATS (128*264 + 32*264 + 32*136 + 32*132 + 256 + 256 + 256)
__global__ __launch_bounds__(512) void k_s1atb(float* __restrict__ s1out)
{
    extern __shared__ float sm[];
    float* Wc   = sm;
    float* Ssm  = Wc  + 128*264;
    float* m2s  = Ssm + 32*264;
    float* As   = m2s + 32*136;
    float* bc   = As  + 32*132;
    float* redm = bc  + 256;
    float* reds = redm + 256;

    int tid = threadIdx.x;
    int w = tid >> 5, lane = tid & 31;
    int gid = lane >> 2, tid4 = lane & 3;
    int chunk = blockIdx.x;
    int k_begin = (int)((long long)NN * chunk / SCHUNKS);
    int k_end   = (int)((long long)NN * (chunk+1) / SCHUNKS);

    int mhalf = (w >> 3) * 16, ncol0 = (w & 7) * 32;
    int msubT = (w >> 1) * 32, nsubT = (w & 1) * 64;

    {
        int r = tid >> 2, cs = (tid & 3) * 64;
        #pragma unroll
        for (int i = 0; i < 16; i++) {
            float4 v = *(const float4*)(g_Wcomb + (size_t)r*256 + cs + i*4);
            Wc[r*264+cs+i*4+0] = to_tf32(v.x); Wc[r*264+cs+i*4+1] = to_tf32(v.y);
            Wc[r*264+cs+i*4+2] = to_tf32(v.z); Wc[r*264+cs+i*4+3] = to_tf32(v.w);
        }
    }
    if (tid < 256) bc[tid] = g_bcomb[tid];

    float accT[2][8][4];
    #pragma unroll
    for (int mf = 0; mf < 2; mf++)
        #pragma unroll
        for (int nf = 0; nf < 8; nf++)
            #pragma unroll
            for (int q = 0; q < 4; q++) accT[mf][nf][q] = 0.f;
    float colacc = 0.f;

    __syncthreads();

    for (int s0 = k_begin; s0 < k_end; s0 += 32) {
        {
            int r = tid >> 4, cs = (tid & 15) * 8;
            int gk = s0 + r;
            float4 v0 = make_float4(0.f,0.f,0.f,0.f), v1 = v0, u0 = v0, u1 = v0;
            if (gk < k_end) {
                v0 = *(const float4*)(g_magg + (size_t)gk*128 + cs);
                v1 = *(const float4*)(g_magg + (size_t)gk*128 + cs + 4);
                u0 = *(const float4*)(g_m2   + (size_t)gk*128 + cs);
                u1 = *(const float4*)(g_m2   + (size_t)gk*128 + cs + 4);
            }
            As[r*132+cs+0] = to_tf32(v0.x); As[r*132+cs+1] = to_tf32(v0.y);
            As[r*132+cs+2] = to_tf32(v0.z); As[r*132+cs+3] = to_tf32(v0.w);
            As[r*132+cs+4] = to_tf32(v1.x); As[r*132+cs+5] = to_tf32(v1.y);
            As[r*132+cs+6] = to_tf32(v1.z); As[r*132+cs+7] = to_tf32(v1.w);
            m2s[r*136+cs+0] = to_tf32(u0.x); m2s[r*136+cs+1] = to_tf32(u0.y);
            m2s[r*136+cs+2] = to_tf32(u0.z); m2s[r*136+cs+3] = to_tf32(u0.w);
            m2s[r*136+cs+4] = to_tf32(u1.x); m2s[r*136+cs+5] = to_tf32(u1.y);
            m2s[r*136+cs+6] = to_tf32(u1.z); m2s[r*136+cs+7] = to_tf32(u1.w);
        }
        __syncthreads();

        float sacc[4][4];
        #pragma unroll
        for (int nf = 0; nf < 4; nf++)
            #pragma unroll
            for (int q = 0; q < 4; q++) sacc[nf][q] = 0.f;
        #pragma unroll
        for (int kk = 0; kk < 16; kk++) {
            int kb = kk*8;
            uint32_t a0 = fbits(As[(mhalf+gid)*132   + kb + tid4    ]);
            uint32_t a1 = fbits(As[(mhalf+gid+8)*132 + kb + tid4    ]);
            uint32_t a2 = fbits(As[(mhalf+gid)*132   + kb + tid4 + 4]);
            uint32_t a3 = fbits(As[(mhalf+gid+8)*132 + kb + tid4 + 4]);
            #pragma unroll
            for (int nf = 0; nf < 4; nf++) {
                int c = ncol0 + nf*8 + gid;
                uint32_t b0 = fbits(Wc[(kb+tid4)*264 + c]);
                uint32_t b1 = fbits(Wc[(kb+tid4+4)*264 + c]);
                mma_tf32(sacc[nf], a0, a1, a2, a3, b0, b1);
            }
        }
        #pragma unroll
        for (int nf = 0; nf < 4; nf++) {
            int c0 = ncol0 + nf*8 + 2*tid4;
            sacc[nf][0] += bc[c0];   sacc[nf][1] += bc[c0+1];
            sacc[nf][2] += bc[c0];   sacc[nf][3] += bc[c0+1];
        }
        {
            float mA = -FLT_MAX, mB = -FLT_MAX;
            #pragma unroll
            for (int nf = 0; nf < 4; nf++) {
                mA = fmaxf(mA, fmaxf(sacc[nf][0], sacc[nf][1]));
                mB = fmaxf(mB, fmaxf(sacc[nf][2], sacc[nf][3]));
            }
            mA = fmaxf(mA, __shfl_xor_sync(0xffffffffu, mA, 1));
            mA = fmaxf(mA, __shfl_xor_sync(0xffffffffu, mA, 2));
            mB = fmaxf(mB, __shfl_xor_sync(0xffffffffu, mB, 1));
            mB = fmaxf(mB, __shfl_xor_sync(0xffffffffu, mB, 2));
            if (tid4 == 0) {
                redm[(mhalf+gid)*8   + (w & 7)] = mA;
                redm[(mhalf+gid+8)*8 + (w & 7)] = mB;
            }
        }
        __syncthreads();
        float rmaxA = -FLT_MAX, rmaxB = -FLT_MAX;
        #pragma unroll
        for (int q = 0; q < 8; q++) {
            rmaxA = fmaxf(rmaxA, redm[(mhalf+gid)*8 + q]);
            rmaxB = fmaxf(rmaxB, redm[(mhalf+gid+8)*8 + q]);
        }
        {
            float sA = 0.f, sB = 0.f;
            #pragma unroll
            for (int nf = 0; nf < 4; nf++) {
                sacc[nf][0] = __expf(sacc[nf][0] - rmaxA);
                sacc[nf][1] = __expf(sacc[nf][1] - rmaxA);
                sacc[nf][2] = __expf(sacc[nf][2] - rmaxB);
                sacc[nf][3] = __expf(sacc[nf][3] - rmaxB);
                sA += sacc[nf][0] + sacc[nf][1];
                sB += sacc[nf][2] + sacc[nf][3];
            }
            sA += __shfl_xor_sync(0xffffffffu, sA, 1);
            sA += __shfl_xor_sync(0xffffffffu, sA, 2);
            sB += __shfl_xor_sync(0xffffffffu, sB, 1);
            sB += __shfl_xor_sync(0xffffffffu, sB, 2);
            if (tid4 == 0) {
                reds[(mhalf+gid)*8   + (w & 7)] = sA;
                reds[(mhalf+gid+8)*8 + (w & 7)] = sB;
            }
        }
        __syncthreads();
        {
            float ssA = 0.f, ssB = 0.f;
            #pragma unroll
            for (int q = 0; q < 8; q++) {
                ssA += reds[(mhalf+gid)*8 + q];
                ssB += reds[(mhalf+gid+8)*8 + q];
            }
            float rinvA = 1.0f / ssA, rinvB = 1.0f / ssB;
            int grA = s0 + mhalf + gid, grB = grA + 8;
            bool vA = (grA < k_end), vB = (grB < k_end);
            #pragma unroll
            for (int nf = 0; nf < 4; nf++) {
                int c0 = ncol0 + nf*8 + 2*tid4;
                float oA0 = vA ? sacc[nf][0]*rinvA : 0.f;
                float oA1 = vA ? sacc[nf][1]*rinvA : 0.f;
                float oB0 = vB ? sacc[nf][2]*rinvB : 0.f;
                float oB1 = vB ? sacc[nf][3]*rinvB : 0.f;
                Ssm[(mhalf+gid)*264 + c0]     = oA0;
                Ssm[(mhalf+gid)*264 + c0 + 1] = oA1;
                Ssm[(mhalf+gid+8)*264 + c0]     = oB0;
                Ssm[(mhalf+gid+8)*264 + c0 + 1] = oB1;
                if (vA) { float2 o; o.x = oA0; o.y = oA1; *(float2*)(s1out + (size_t)grA*256 + c0) = o; }
                if (vB) { float2 o; o.x = oB0; o.y = oB1; *(float2*)(s1out + (size_t)grB*256 + c0) = o; }
            }
        }
        __syncthreads();

        if (tid < 256) {
            #pragma unroll 8
            for (int r = 0; r < 32; r++) colacc += Ssm[r*264 + tid];
        }
        #pragma unroll
        for (int kk = 0; kk < 4; kk++) {
            int kb = kk*8;
            uint32_t a[2][4];
            #pragma unroll
            for (int mf = 0; mf < 2; mf++) {
                int m = msubT + mf*16 + gid;
                a[mf][0] = fbits(Ssm[(kb+tid4)*264   + m  ]);
                a[mf][1] = fbits(Ssm[(kb+tid4)*264   + m+8]);
                a[mf][2] = fbits(Ssm[(kb+tid4+4)*264 + m  ]);
                a[mf][3] = fbits(Ssm[(kb+tid4+4)*264 + m+8]);
            }
            #pragma unroll
            for (int nf = 0; nf < 8; nf++) {
                int c = nsubT + nf*8 + gid;
                uint32_t b0 = fbits(m2s[(kb+tid4)*136 + c]);
                uint32_t b1 = fbits(m2s[(kb+tid4+4)*136 + c]);
                mma_tf32(accT[0][nf], a[0][0], a[0][1], a[0][2], a[0][3], b0, b1);
                mma_tf32(accT[1][nf], a[1][0], a[1][1], a[1][2], a[1][3], b0, b1);
            }
        }
        __syncthreads();
    }

    float* P = g_part + (size_t)chunk * (CC1*DD);
    #pragma unroll
    for (int mf = 0; mf < 2; mf++) {
        int mloc = msubT + mf*16 + gid;
        #pragma unroll
        for (int nf = 0; nf < 8; nf++) {
            int c0 = nsubT + nf*8 + 2*tid4;
            float2 lo; lo.x = accT[mf][nf][0]; lo.y = accT[mf][nf][1];
            float2 hi; hi.x = accT[mf][nf][2]; hi.y = accT[mf][nf][3];
            *(float2*)(P + (size_t)mloc*128 + c0)     = lo;
            *(float2*)(P + (size_t)(mloc+8)*128 + c0) = hi;
        }
    }
    #pragma unroll
    for (int nf = 0; nf < 8; nf++) {
        float cs0 = accT[0][nf][0] + accT[0][nf][2] + accT[1][nf][0] + accT[1][nf][2];
        float cs1 = accT[0][nf][1] + accT[0][nf][3] + accT[1][nf][1] + accT[1][nf][3];
        #pragma unroll
        for (int o = 4; o < 32; o <<= 1) {
            cs0 += __shfl_xor_sync(0xffffffffu, cs0, o);
            cs1 += __shfl_xor_sync(0xffffffffu, cs1, o);
        }
        if (gid == 0) {
            int c0 = nsubT + nf*8 + 2*tid4;
            atomicAdd(&g_sumT[c0],   cs0);
            atomicAdd(&g_sumT[c0+1], cs1);
        }
    }
    if (tid < 256) atomicAdd(&g_colsum[tid], colacc);
}

// ============================ x1 + analytic coarse tail (merged) ============================
__global__ __launch_bounds__(256) void k_x1tail(
    const float* __restrict__ We1, const float* __restrict__ be1,
    const float* __restrict__ We2, const float* __restrict__ be2,
    const float* __restrict__ Wa2, const float* __restrict__ ba2,
    float* __restrict__ out)
{
    int t = threadIdx.x;
    if (blockIdx.x < 128) {
        __shared__ float sT[2][128];
        int rowsel = t >> 7;
        int d = t & 127;
        int k = blockIdx.x*2 + rowsel;
        float s = 0.f;
        #pragma unroll 4
        for (int c = 0; c < SCHUNKS; c++)
            s += g_part[(size_t)c*(CC1*DD) + (size_t)k*128 + d];
        sT[rowsel][d] = s;
        __syncthreads();
        float colk = g_colsum[k];
        float acc = 0.f;
        #pragma unroll 8
        for (int e = 0; e < 128; e++) acc = fmaf(sT[rowsel][e], We1[e*128 + d], acc);
        out[OFF_X1 + k*128 + d] = acc + colk * be1[d];
        return;
    }
    // tail block
    __shared__ float sumT[128];
    __shared__ float meanx1[128];
    __shared__ float meanvec[128];
    __shared__ float s2row[32];
    __shared__ float sc[256];

    if (t < 128) sumT[t] = g_sumT[t];
    sc[t] = g_colsum[t];
    __syncthreads();
    #pragma unroll
    for (int st = 128; st > 0; st >>= 1) {
        if (t < st) sc[t] += sc[t+st];
        __syncthreads();
    }
    float sumcol = sc[0];
    if (t < 128) {
        float s = 0.f;
        for (int e = 0; e < 128; e++) s = fmaf(sumT[e], We1[e*128 + t], s);
        meanx1[t] = (s + sumcol*be1[t]) * (1.0f/256.0f);
    }
    __syncthreads();
    if (t < 128) {
        float s = 0.f;
        for (int e = 0; e < 128; e++) s = fmaf(meanx1[e], We2[e*128 + t], s);
        meanvec[t] = s + be2[t];
    }
    __syncthreads();
    if (t < 32) {
        float s = 0.f;
        for (int d = 0; d < 128; d++) s = fmaf(meanvec[d], Wa2[d*32 + t], s);
        float v = s + ba2[t];
        float mx = v;
        #pragma unroll
        for (int o = 16; o > 0; o >>= 1) mx = fmaxf(mx, __shfl_xor_sync(0xffffffffu, mx, o));
        float ex = __expf(v - mx);
        float sm = ex;
        #pragma unroll
        for (int o = 16; o > 0; o >>= 1) sm += __shfl_xor_sync(0xffffffffu, sm, o);
        s2row[t] = ex / sm;
    }
    __syncthreads();
    for (int i = t; i < 256*32; i += 256) out[OFF_S2 + i] = s2row[i & 31];
    if (t < 32) out[OFF_A1 + t] = 1.0f;
    for (int i = t; i < 32*128; i += 256)
        out[OFF_X2 + i] = 256.0f * s2row[i >> 7] * meanvec[i & 127];
    if (t == 0) {
        float s = 0.f;
        for (int d = 0; d < 128; d++) s += meanvec[d];
        out[OFF_E0] = s * (1.0f/16.0f);
    }
}

// ============================ launch ============================
extern "C" void kernel_launch(void* const* d_in, const int* in_sizes, int n_in,
                              void* d_out, int out_size)
{
    const float* feature = (const float*)d_in[0];
    const int*   eidx    = (const int*)d_in[1];
    const int*   src     = eidx;
    const int*   dst     = eidx + EE;
    const float* Wf   = (const float*)d_in[2];
    const float* bf   = (const float*)d_in[3];
    const float* We1  = (const float*)d_in[4];
    const float* be1  = (const float*)d_in[5];
    const float* Wa1  = (const float*)d_in[6];
    const float* ba1  = (const float*)d_in[7];
    const float* attW1 = (const float*)d_in[8];
    const float* attb1 = (const float*)d_in[9];
    const float* We2  = (const float*)d_in[10];
    const float* be2  = (const float*)d_in[11];
    const float* Wa2  = (const float*)d_in[12];
    const float* ba2  = (const float*)d_in[13];
    float* out = (float*)d_out;

    float *zf_p, *m2_p;
    cudaGetSymbolAddress((void**)&zf_p, g_zf);
    cudaGetSymbolAddress((void**)&m2_p, g_m2);

    const int zf_smem = (128*36*2 + 32*136*2) * 4;         // 71680 B
    const int s1atb_smem = S1ATB_SMEM_FLOATS * 4;          // 206336 B
    cudaFuncSetAttribute(k_gemm_zf_fold, cudaFuncAttributeMaxDynamicSharedMemorySize, zf_smem);
    cudaFuncSetAttribute(k_s1atb, cudaFuncAttributeMaxDynamicSharedMemorySize, s1atb_smem);

    cudaStream_t side = g_sr.s;

    // ---- fork ----
    cudaEventRecord(g_sr.fork, 0);

    // main stream: single persistent graph-build kernel (launch #0)
    k_graph<<<148, 1024>>>(src, dst);

    // side stream: zf GEMM + fold merged (launch #1)
    cudaStreamWaitEvent(side, g_sr.fork, 0);
    k_gemm_zf_fold<<<ZF_BLOCKS + 129, 256, zf_smem, side>>>(
        feature, Wf, bf, zf_p, We1, be1, Wa1, ba1, attW1);
    cudaEventRecord(g_sr.join, side);

    // ---- join, then serial chain ----
    cudaStreamWaitEvent(0, g_sr.join, 0);

    // launch #2: embed3 = x = normalize(segmean(zf))
    k_segmean<true,false><<<(NN+31)/32, 256>>>(zf_p, out + OFF_E3);
    // launch #3 (ncu capture target): m2 = segmean(x) + fused dots
    k_segmean<false,true><<<(NN+31)/32, 256>>>(out + OFF_E3, m2_p);
    // launch #4: GAT aggregation
    k_gatagg<<<(NN+31)/32, 256>>>(attb1);
    // launch #5: FUSED s1 softmax GEMM + T partials + sumT/colsum
    k_s1atb<<<SCHUNKS, 512, s1atb_smem>>>(out + OFF_S1);
    // launch #6: x1 + analytic tail
    k_x1tail<<<129, 256>>>(We1, be1, We2, be2, Wa2, ba2, out);
}

// round 15
// speedup vs baseline: 1.3746x; 1.3746x over previous
#include <cuda_runtime.h>
#include <math.h>
#include <float.h>
#include <stdint.h>

#define NN   20000
#define EE   340000
#define DD   128
#define CC1  256
#define SCHUNKS 148   // fused s1+atb chunks: 1 block/SM
#define SCANB 20      // ceil(NN/1024)

// ---- output layout (element offsets into float* d_out) ----
#define OFF_S1  0
#define OFF_S2  (NN*CC1)
#define OFF_A1  (OFF_S2 + 256*32)
#define OFF_E3  (OFF_A1 + 32)
#define OFF_X1  (OFF_E3 + NN*DD)
#define OFF_X2  (OFF_X1 + 256*128)
#define OFF_E0  (OFF_X2 + 32*128)

// ---- scratch ----
__device__ float g_zf[NN*DD];
__device__ float g_m2[NN*DD];
__device__ float g_magg[NN*DD];
__device__ float g_asrc[NN];
__device__ float g_adst[NN];
__device__ int   g_deg[NN];
__device__ int   g_off[NN+1];
__device__ int   g_cur[NN];
__device__ int   g_csrc[EE];
__device__ float g_Wcomb[DD*CC1];        // 128x256
__device__ float g_bcomb[CC1];
__device__ float g_us[DD];
__device__ float g_ud[DD];
__device__ float g_cs[2];
__device__ float g_part[SCHUNKS*CC1*DD]; // per-chunk T partials (19.4MB)
__device__ float g_colsum[CC1];
__device__ float g_sumT[DD];

// ---- persistent side stream + events ----
struct SideRes {
    cudaStream_t s;
    cudaEvent_t fork, join;
    SideRes() {
        cudaStreamCreateWithFlags(&s, cudaStreamNonBlocking);
        cudaEventCreateWithFlags(&fork, cudaEventDisableTiming);
        cudaEventCreateWithFlags(&join, cudaEventDisableTiming);
    }
};
static SideRes g_sr;

// ---- tf32 helpers ----
__device__ __forceinline__ float to_tf32(float x) {
    float r;
    asm("cvt.rna.tf32.f32 %0, %1;" : "=f"(r) : "f"(x));
    return r;
}
__device__ __forceinline__ void mma_tf32(float c[4],
    uint32_t a0, uint32_t a1, uint32_t a2, uint32_t a3,
    uint32_t b0, uint32_t b1)
{
    asm volatile(
        "mma.sync.aligned.m16n8k8.row.col.f32.tf32.tf32.f32 "
        "{%0,%1,%2,%3},{%4,%5,%6,%7},{%8,%9},{%0,%1,%2,%3};\n"
        : "+f"(c[0]), "+f"(c[1]), "+f"(c[2]), "+f"(c[3])
        : "r"(a0), "r"(a1), "r"(a2), "r"(a3), "r"(b0), "r"(b1));
}
__device__ __forceinline__ uint32_t fbits(float x) { return __float_as_uint(x); }

// ============================ graph build ============================
__global__ void k_count(const int* __restrict__ dst) {
    int e = blockIdx.x*blockDim.x + threadIdx.x;
    if (e < EE) atomicAdd(&g_deg[dst[e]], 1);
}

__global__ __launch_bounds__(1024) void k_scanall() {
    __shared__ int sh[1024];
    int t = threadIdx.x, b = blockIdx.x;
    int base = 0;
    for (int i = t; i < b*1024; i += 1024) base += g_deg[i];
    sh[t] = base; __syncthreads();
    #pragma unroll
    for (int st = 512; st > 0; st >>= 1) {
        if (t < st) sh[t] += sh[t+st];
        __syncthreads();
    }
    base = sh[0];
    __syncthreads();
    int i = b*1024 + t;
    int d = (i < NN) ? g_deg[i] : 0;
    sh[t] = d; __syncthreads();
    #pragma unroll
    for (int off = 1; off < 1024; off <<= 1) {
        int v = (t >= off) ? sh[t-off] : 0;
        __syncthreads();
        sh[t] += v;
        __syncthreads();
    }
    int excl = base + sh[t] - d;
    if (i < NN) { g_off[i] = excl; g_cur[i] = excl; }
    if (i == 0) g_off[NN] = EE;
}

__global__ void k_fill(const int* __restrict__ src, const int* __restrict__ dst) {
    int e = blockIdx.x*blockDim.x + threadIdx.x;
    if (e < EE) {
        int p = atomicAdd(&g_cur[dst[e]], 1);
        g_csrc[p] = src[e];
    }
}

// ============================ weight folding (+ zero accumulators) ============================
__global__ __launch_bounds__(256) void k_fold(
    const float* __restrict__ We1, const float* __restrict__ be1,
    const float* __restrict__ Wa1, const float* __restrict__ ba1,
    const float* __restrict__ attW)
{
    int b = blockIdx.x, t = threadIdx.x;
    if (b < 128) {
        __shared__ float sWe[128];
        if (t < 128) sWe[t] = We1[b*128 + t];
        __syncthreads();
        float acc = 0.f;
        #pragma unroll 8
        for (int k = 0; k < 128; k++) acc = fmaf(sWe[k], Wa1[k*256 + t], acc);
        g_Wcomb[b*256 + t] = acc;
    } else {
        __shared__ float ts[128], td[128], bc[256];
        g_colsum[t] = 0.f;
        if (t < 128) g_sumT[t] = 0.f;
        if (t < 128) {
            float s1v = 0.f, s2v = 0.f;
            for (int c = 0; c < 256; c++) {
                float w = Wa1[t*256 + c];
                s1v = fmaf(w, attW[c], s1v);
                s2v = fmaf(w, attW[256 + c], s2v);
            }
            ts[t] = s1v; td[t] = s2v;
        }
        {
            float s = 0.f;
            for (int e = 0; e < 128; e++) s = fmaf(be1[e], Wa1[e*256 + t], s);
            bc[t] = s + ba1[t];
            g_bcomb[t] = bc[t];
        }
        __syncthreads();
        if (t < 128) {
            float u1 = 0.f, u2 = 0.f;
            for (int e = 0; e < 128; e++) {
                float w = We1[t*128 + e];
                u1 = fmaf(w, ts[e], u1);
                u2 = fmaf(w, td[e], u2);
            }
            g_us[t] = u1; g_ud[t] = u2;
        }
        if (t == 0) {
            float c1v = 0.f, c2v = 0.f;
            for (int c = 0; c < 256; c++) {
                c1v = fmaf(bc[c], attW[c], c1v);
                c2v = fmaf(bc[c], attW[256 + c], c2v);
            }
            g_cs[0] = c1v; g_cs[1] = c2v;
        }
    }
}

// ============================ zf = feature@Wf + bf : split-TF32 MMA ============================
__global__ __launch_bounds__(256) void k_gemm_zf(
    const float* __restrict__ A, const float* __restrict__ B,
    const float* __restrict__ bias, float* __restrict__ C)
{
    extern __shared__ float zs[];
    float* Ahi = zs;
    float* Alo = Ahi + 128*36;
    float* Bhi = Alo + 128*36;
    float* Blo = Bhi + 32*136;

    int tid = threadIdx.x;
    int w = tid >> 5, lane = tid & 31;
    int gid = lane >> 2, tid4 = lane & 3;
    int msub = (w >> 1) * 32, nsub = (w & 1) * 64;
    int row0 = blockIdx.x * 128;

    float acc[2][8][4];
    #pragma unroll
    for (int mf = 0; mf < 2; mf++)
        #pragma unroll
        for (int nf = 0; nf < 8; nf++)
            #pragma unroll
            for (int q = 0; q < 4; q++) acc[mf][nf][q] = 0.f;

    for (int k0 = 0; k0 < 128; k0 += 32) {
        {
            int r = tid >> 1, cs = (tid & 1) * 16;
            int gr = row0 + r;
            #pragma unroll
            for (int i = 0; i < 4; i++) {
                float4 v = make_float4(0.f,0.f,0.f,0.f);
                if (gr < NN) v = *(const float4*)(A + (size_t)gr*128 + k0 + cs + i*4);
                float hx = to_tf32(v.x), hy = to_tf32(v.y), hz = to_tf32(v.z), hw = to_tf32(v.w);
                Ahi[r*36+cs+i*4+0] = hx; Alo[r*36+cs+i*4+0] = to_tf32(v.x - hx);
                Ahi[r*36+cs+i*4+1] = hy; Alo[r*36+cs+i*4+1] = to_tf32(v.y - hy);
                Ahi[r*36+cs+i*4+2] = hz; Alo[r*36+cs+i*4+2] = to_tf32(v.z - hz);
                Ahi[r*36+cs+i*4+3] = hw; Alo[r*36+cs+i*4+3] = to_tf32(v.w - hw);
            }
        }
        {
            int r = tid >> 3, cs = (tid & 7) * 16;
            #pragma unroll
            for (int i = 0; i < 4; i++) {
                float4 v = *(const float4*)(B + (size_t)(k0+r)*128 + cs + i*4);
                float hx = to_tf32(v.x), hy = to_tf32(v.y), hz = to_tf32(v.z), hw = to_tf32(v.w);
                Bhi[r*136+cs+i*4+0] = hx; Blo[r*136+cs+i*4+0] = to_tf32(v.x - hx);
                Bhi[r*136+cs+i*4+1] = hy; Blo[r*136+cs+i*4+1] = to_tf32(v.y - hy);
                Bhi[r*136+cs+i*4+2] = hz; Blo[r*136+cs+i*4+2] = to_tf32(v.z - hz);
                Bhi[r*136+cs+i*4+3] = hw; Blo[r*136+cs+i*4+3] = to_tf32(v.w - hw);
            }
        }
        __syncthreads();
        #pragma unroll
        for (int kk = 0; kk < 4; kk++) {
            int kb = kk*8;
            uint32_t ah[2][4], al[2][4];
            #pragma unroll
            for (int mf = 0; mf < 2; mf++) {
                int m = msub + mf*16 + gid;
                ah[mf][0] = fbits(Ahi[m*36     + kb + tid4    ]);
                ah[mf][1] = fbits(Ahi[(m+8)*36 + kb + tid4    ]);
                ah[mf][2] = fbits(Ahi[m*36     + kb + tid4 + 4]);
                ah[mf][3] = fbits(Ahi[(m+8)*36 + kb + tid4 + 4]);
                al[mf][0] = fbits(Alo[m*36     + kb + tid4    ]);
                al[mf][1] = fbits(Alo[(m+8)*36 + kb + tid4    ]);
                al[mf][2] = fbits(Alo[m*36     + kb + tid4 + 4]);
                al[mf][3] = fbits(Alo[(m+8)*36 + kb + tid4 + 4]);
            }
            #pragma unroll
            for (int nf = 0; nf < 8; nf++) {
                int c = nsub + nf*8 + gid;
                uint32_t bh0 = fbits(Bhi[(kb+tid4)*136 + c]);
                uint32_t bh1 = fbits(Bhi[(kb+tid4+4)*136 + c]);
                uint32_t bl0 = fbits(Blo[(kb+tid4)*136 + c]);
                uint32_t bl1 = fbits(Blo[(kb+tid4+4)*136 + c]);
                #pragma unroll
                for (int mf = 0; mf < 2; mf++) {
                    mma_tf32(acc[mf][nf], ah[mf][0], ah[mf][1], ah[mf][2], ah[mf][3], bh0, bh1);
                    mma_tf32(acc[mf][nf], ah[mf][0], ah[mf][1], ah[mf][2], ah[mf][3], bl0, bl1);
                    mma_tf32(acc[mf][nf], al[mf][0], al[mf][1], al[mf][2], al[mf][3], bh0, bh1);
                }
            }
        }
        __syncthreads();
    }
    #pragma unroll
    for (int mf = 0; mf < 2; mf++) {
        int rlo = row0 + msub + mf*16 + gid;
        int rhi = rlo + 8;
        #pragma unroll
        for (int nf = 0; nf < 8; nf++) {
            int c0 = nsub + nf*8 + 2*tid4;
            float b0v = bias[c0], b1v = bias[c0+1];
            if (rlo < NN) {
                float2 o; o.x = acc[mf][nf][0]+b0v; o.y = acc[mf][nf][1]+b1v;
                *(float2*)(C + (size_t)rlo*128 + c0) = o;
            }
            if (rhi < NN) {
                float2 o; o.x = acc[mf][nf][2]+b0v; o.y = acc[mf][nf][3]+b1v;
                *(float2*)(C + (size_t)rhi*128 + c0) = o;
            }
        }
    }
}

// ============================ segment mean (2 nodes/warp -> high occupancy) ============================
template<bool NORM, bool DOTS>
__global__ __launch_bounds__(256) void k_segmean(
    const float* __restrict__ zin, float* __restrict__ out)
{
    int warp = threadIdx.x >> 5, lane = threadIdx.x & 31;
    int node0 = (blockIdx.x*8 + warp) * 2;
    if (node0 >= NN) return;
    int offv = 0;
    if (lane < 3) offv = g_off[min(node0 + lane, NN)];
    const float* zl = zin + lane*4;
    float4 us4, ud4;
    if (DOTS) {
        us4 = *(const float4*)(g_us + lane*4);
        ud4 = *(const float4*)(g_ud + lane*4);
    }

    #pragma unroll
    for (int ni = 0; ni < 2; ni++) {
        int node = node0 + ni;
        if (node >= NN) break;
        int e0 = __shfl_sync(0xffffffffu, offv, ni);
        int e1 = __shfl_sync(0xffffffffu, offv, ni+1);
        float4 acc = make_float4(0.f,0.f,0.f,0.f);
        for (int base = e0; base < e1; base += 32) {
            int j = base + lane;
            int myidx = (j < e1) ? g_csrc[j] : 0;
            int cnt = min(32, e1 - base);
            int t = 0;
            for (; t + 4 <= cnt; t += 4) {
                int s0 = __shfl_sync(0xffffffffu, myidx, t);
                int s1i = __shfl_sync(0xffffffffu, myidx, t+1);
                int s2 = __shfl_sync(0xffffffffu, myidx, t+2);
                int s3 = __shfl_sync(0xffffffffu, myidx, t+3);
                float4 v0 = *(const float4*)(zl + (size_t)s0*DD);
                float4 v1 = *(const float4*)(zl + (size_t)s1i*DD);
                float4 v2 = *(const float4*)(zl + (size_t)s2*DD);
                float4 v3 = *(const float4*)(zl + (size_t)s3*DD);
                acc.x += (v0.x+v1.x) + (v2.x+v3.x);
                acc.y += (v0.y+v1.y) + (v2.y+v3.y);
                acc.z += (v0.z+v1.z) + (v2.z+v3.z);
                acc.w += (v0.w+v1.w) + (v2.w+v3.w);
            }
            for (; t < cnt; t++) {
                int sb = __shfl_sync(0xffffffffu, myidx, t);
                float4 v = *(const float4*)(zl + (size_t)sb*DD);
                acc.x += v.x; acc.y += v.y; acc.z += v.z; acc.w += v.w;
            }
        }
        float inv = 1.0f / (float)(e1 - e0);
        acc.x *= inv; acc.y *= inv; acc.z *= inv; acc.w *= inv;
        if (NORM) {
            float ss = acc.x*acc.x + acc.y*acc.y + acc.z*acc.z + acc.w*acc.w;
            #pragma unroll
            for (int o = 16; o > 0; o >>= 1) ss += __shfl_xor_sync(0xffffffffu, ss, o);
            float r = 1.0f / fmaxf(sqrtf(ss), 1e-12f);
            acc.x *= r; acc.y *= r; acc.z *= r; acc.w *= r;
        }
        *(float4*)(out + (size_t)node*DD + lane*4) = acc;
        if (DOTS) {
            float as = acc.x*us4.x + acc.y*us4.y + acc.z*us4.z + acc.w*us4.w;
            float ad = acc.x*ud4.x + acc.y*ud4.y + acc.z*ud4.z + acc.w*ud4.w;
            #pragma unroll
            for (int o = 16; o > 0; o >>= 1) {
                as += __shfl_xor_sync(0xffffffffu, as, o);
                ad += __shfl_xor_sync(0xffffffffu, ad, o);
            }
            if (lane == 0) { g_asrc[node] = as + g_cs[0]; g_adst[node] = ad + g_cs[1]; }
        }
    }
}

// ============================ GAT aggregation (2 nodes/warp) ============================
__global__ __launch_bounds__(256) void k_gatagg(const float* __restrict__ attb)
{
    int warp = threadIdx.x >> 5, lane = threadIdx.x & 31;
    int node0 = (blockIdx.x*8 + warp) * 2;
    if (node0 >= NN) return;
    int offv = 0;
    if (lane < 3) offv = g_off[min(node0 + lane, NN)];
    float adv = 0.f;
    if (lane < 2) adv = g_adst[min(node0 + lane, NN-1)];
    float attb0 = attb[0];
    const float* zl = g_m2 + lane*4;

    #pragma unroll
    for (int ni = 0; ni < 2; ni++) {
        int node = node0 + ni;
        if (node >= NN) break;
        int e0 = __shfl_sync(0xffffffffu, offv, ni);
        int e1 = __shfl_sync(0xffffffffu, offv, ni+1);
        float adb = __shfl_sync(0xffffffffu, adv, ni) + attb0;

        float mx = -FLT_MAX;
        for (int j = e0 + lane; j < e1; j += 32) {
            float e = g_asrc[g_csrc[j]] + adb;
            e = (e > 0.f) ? e : 0.01f*e;
            mx = fmaxf(mx, e);
        }
        #pragma unroll
        for (int o = 16; o > 0; o >>= 1) mx = fmaxf(mx, __shfl_xor_sync(0xffffffffu, mx, o));

        float4 acc = make_float4(0.f,0.f,0.f,0.f);
        float denom = 0.f;
        for (int base = e0; base < e1; base += 32) {
            int j = base + lane;
            int s = 0; float a = 0.f;
            if (j < e1) {
                s = g_csrc[j];
                float e = g_asrc[s] + adb;
                e = (e > 0.f) ? e : 0.01f*e;
                a = __expf(e - mx);
                denom += a;
            }
            int cnt = min(32, e1 - base);
            int t = 0;
            for (; t + 4 <= cnt; t += 4) {
                float a0 = __shfl_sync(0xffffffffu, a, t);
                float a1 = __shfl_sync(0xffffffffu, a, t+1);
                float a2 = __shfl_sync(0xffffffffu, a, t+2);
                float a3 = __shfl_sync(0xffffffffu, a, t+3);
                int   s0 = __shfl_sync(0xffffffffu, s, t);
                int   s1i = __shfl_sync(0xffffffffu, s, t+1);
                int   s2 = __shfl_sync(0xffffffffu, s, t+2);
                int   s3 = __shfl_sync(0xffffffffu, s, t+3);
                float4 v0 = *(const float4*)(zl + (size_t)s0*DD);
                float4 v1 = *(const float4*)(zl + (size_t)s1i*DD);
                float4 v2 = *(const float4*)(zl + (size_t)s2*DD);
                float4 v3 = *(const float4*)(zl + (size_t)s3*DD);
                acc.x = fmaf(a0, v0.x, fmaf(a1, v1.x, fmaf(a2, v2.x, fmaf(a3, v3.x, acc.x))));
                acc.y = fmaf(a0, v0.y, fmaf(a1, v1.y, fmaf(a2, v2.y, fmaf(a3, v3.y, acc.y))));
                acc.z = fmaf(a0, v0.z, fmaf(a1, v1.z, fmaf(a2, v2.z, fmaf(a3, v3.z, acc.z))));
                acc.w = fmaf(a0, v0.w, fmaf(a1, v1.w, fmaf(a2, v2.w, fmaf(a3, v3.w, acc.w))));
            }
            for (; t < cnt; t++) {
                float ab = __shfl_sync(0xffffffffu, a, t);
                int   sb = __shfl_sync(0xffffffffu, s, t);
                float4 v = *(const float4*)(zl + (size_t)sb*DD);
                acc.x = fmaf(ab, v.x, acc.x); acc.y = fmaf(ab, v.y, acc.y);
                acc.z = fmaf(ab, v.z, acc.z); acc.w = fmaf(ab, v.w, acc.w);
            }
        }
        #pragma unroll
        for (int o = 16; o > 0; o >>= 1) denom += __shfl_xor_sync(0xffffffffu, denom, o);
        float r = 1.0f / denom;
        acc.x *= r; acc.y *= r; acc.z *= r; acc.w *= r;
        *(float4*)(g_magg + (size_t)node*DD + lane*4) = acc;
    }
}

// ============================ FUSED: s1 softmax GEMM + T partials + sumT/colsum ============================
#define S1ATB_SMEM_FLOATS (128*264 + 32*264 + 32*136 + 32*132 + 256 + 256 + 256)
__global__ __launch_bounds__(512) void k_s1atb(float* __restrict__ s1out)
{
    extern __shared__ float sm[];
    float* Wc   = sm;
    float* Ssm  = Wc  + 128*264;
    float* m2s  = Ssm + 32*264;
    float* As   = m2s + 32*136;
    float* bc   = As  + 32*132;
    float* redm = bc  + 256;
    float* reds = redm + 256;

    int tid = threadIdx.x;
    int w = tid >> 5, lane = tid & 31;
    int gid = lane >> 2, tid4 = lane & 3;
    int chunk = blockIdx.x;
    int k_begin = (int)((long long)NN * chunk / SCHUNKS);
    int k_end   = (int)((long long)NN * (chunk+1) / SCHUNKS);

    int mhalf = (w >> 3) * 16, ncol0 = (w & 7) * 32;
    int msubT = (w >> 1) * 32, nsubT = (w & 1) * 64;

    {
        int r = tid >> 2, cs = (tid & 3) * 64;
        #pragma unroll
        for (int i = 0; i < 16; i++) {
            float4 v = *(const float4*)(g_Wcomb + (size_t)r*256 + cs + i*4);
            Wc[r*264+cs+i*4+0] = to_tf32(v.x); Wc[r*264+cs+i*4+1] = to_tf32(v.y);
            Wc[r*264+cs+i*4+2] = to_tf32(v.z); Wc[r*264+cs+i*4+3] = to_tf32(v.w);
        }
    }
    if (tid < 256) bc[tid] = g_bcomb[tid];

    float accT[2][8][4];
    #pragma unroll
    for (int mf = 0; mf < 2; mf++)
        #pragma unroll
        for (int nf = 0; nf < 8; nf++)
            #pragma unroll
            for (int q = 0; q < 4; q++) accT[mf][nf][q] = 0.f;
    float colacc = 0.f;

    __syncthreads();

    for (int s0 = k_begin; s0 < k_end; s0 += 32) {
        {
            int r = tid >> 4, cs = (tid & 15) * 8;
            int gk = s0 + r;
            float4 v0 = make_float4(0.f,0.f,0.f,0.f), v1 = v0, u0 = v0, u1 = v0;
            if (gk < k_end) {
                v0 = *(const float4*)(g_magg + (size_t)gk*128 + cs);
                v1 = *(const float4*)(g_magg + (size_t)gk*128 + cs + 4);
                u0 = *(const float4*)(g_m2   + (size_t)gk*128 + cs);
                u1 = *(const float4*)(g_m2   + (size_t)gk*128 + cs + 4);
            }
            As[r*132+cs+0] = to_tf32(v0.x); As[r*132+cs+1] = to_tf32(v0.y);
            As[r*132+cs+2] = to_tf32(v0.z); As[r*132+cs+3] = to_tf32(v0.w);
            As[r*132+cs+4] = to_tf32(v1.x); As[r*132+cs+5] = to_tf32(v1.y);
            As[r*132+cs+6] = to_tf32(v1.z); As[r*132+cs+7] = to_tf32(v1.w);
            m2s[r*136+cs+0] = to_tf32(u0.x); m2s[r*136+cs+1] = to_tf32(u0.y);
            m2s[r*136+cs+2] = to_tf32(u0.z); m2s[r*136+cs+3] = to_tf32(u0.w);
            m2s[r*136+cs+4] = to_tf32(u1.x); m2s[r*136+cs+5] = to_tf32(u1.y);
            m2s[r*136+cs+6] = to_tf32(u1.z); m2s[r*136+cs+7] = to_tf32(u1.w);
        }
        __syncthreads();

        float sacc[4][4];
        #pragma unroll
        for (int nf = 0; nf < 4; nf++)
            #pragma unroll
            for (int q = 0; q < 4; q++) sacc[nf][q] = 0.f;
        #pragma unroll
        for (int kk = 0; kk < 16; kk++) {
            int kb = kk*8;
            uint32_t a0 = fbits(As[(mhalf+gid)*132   + kb + tid4    ]);
            uint32_t a1 = fbits(As[(mhalf+gid+8)*132 + kb + tid4    ]);
            uint32_t a2 = fbits(As[(mhalf+gid)*132   + kb + tid4 + 4]);
            uint32_t a3 = fbits(As[(mhalf+gid+8)*132 + kb + tid4 + 4]);
            #pragma unroll
            for (int nf = 0; nf < 4; nf++) {
                int c = ncol0 + nf*8 + gid;
                uint32_t b0 = fbits(Wc[(kb+tid4)*264 + c]);
                uint32_t b1 = fbits(Wc[(kb+tid4+4)*264 + c]);
                mma_tf32(sacc[nf], a0, a1, a2, a3, b0, b1);
            }
        }
        #pragma unroll
        for (int nf = 0; nf < 4; nf++) {
            int c0 = ncol0 + nf*8 + 2*tid4;
            sacc[nf][0] += bc[c0];   sacc[nf][1] += bc[c0+1];
            sacc[nf][2] += bc[c0];   sacc[nf][3] += bc[c0+1];
        }
        {
            float mA = -FLT_MAX, mB = -FLT_MAX;
            #pragma unroll
            for (int nf = 0; nf < 4; nf++) {
                mA = fmaxf(mA, fmaxf(sacc[nf][0], sacc[nf][1]));
                mB = fmaxf(mB, fmaxf(sacc[nf][2], sacc[nf][3]));
            }
            mA = fmaxf(mA, __shfl_xor_sync(0xffffffffu, mA, 1));
            mA = fmaxf(mA, __shfl_xor_sync(0xffffffffu, mA, 2));
            mB = fmaxf(mB, __shfl_xor_sync(0xffffffffu, mB, 1));
            mB = fmaxf(mB, __shfl_xor_sync(0xffffffffu, mB, 2));
            if (tid4 == 0) {
                redm[(mhalf+gid)*8   + (w & 7)] = mA;
                redm[(mhalf+gid+8)*8 + (w & 7)] = mB;
            }
        }
        __syncthreads();
        float rmaxA = -FLT_MAX, rmaxB = -FLT_MAX;
        #pragma unroll
        for (int q = 0; q < 8; q++) {
            rmaxA = fmaxf(rmaxA, redm[(mhalf+gid)*8 + q]);
            rmaxB = fmaxf(rmaxB, redm[(mhalf+gid+8)*8 + q]);
        }
        {
            float sA = 0.f, sB = 0.f;
            #pragma unroll
            for (int nf = 0; nf < 4; nf++) {
                sacc[nf][0] = __expf(sacc[nf][0] - rmaxA);
                sacc[nf][1] = __expf(sacc[nf][1] - rmaxA);
                sacc[nf][2] = __expf(sacc[nf][2] - rmaxB);
                sacc[nf][3] = __expf(sacc[nf][3] - rmaxB);
                sA += sacc[nf][0] + sacc[nf][1];
                sB += sacc[nf][2] + sacc[nf][3];
            }
            sA += __shfl_xor_sync(0xffffffffu, sA, 1);
            sA += __shfl_xor_sync(0xffffffffu, sA, 2);
            sB += __shfl_xor_sync(0xffffffffu, sB, 1);
            sB += __shfl_xor_sync(0xffffffffu, sB, 2);
            if (tid4 == 0) {
                reds[(mhalf+gid)*8   + (w & 7)] = sA;
                reds[(mhalf+gid+8)*8 + (w & 7)] = sB;
            }
        }
        __syncthreads();
        {
            float ssA = 0.f, ssB = 0.f;
            #pragma unroll
            for (int q = 0; q < 8; q++) {
                ssA += reds[(mhalf+gid)*8 + q];
                ssB += reds[(mhalf+gid+8)*8 + q];
            }
            float rinvA = 1.0f / ssA, rinvB = 1.0f / ssB;
            int grA = s0 + mhalf + gid, grB = grA + 8;
            bool vA = (grA < k_end), vB = (grB < k_end);
            #pragma unroll
            for (int nf = 0; nf < 4; nf++) {
                int c0 = ncol0 + nf*8 + 2*tid4;
                float oA0 = vA ? sacc[nf][0]*rinvA : 0.f;
                float oA1 = vA ? sacc[nf][1]*rinvA : 0.f;
                float oB0 = vB ? sacc[nf][2]*rinvB : 0.f;
                float oB1 = vB ? sacc[nf][3]*rinvB : 0.f;
                Ssm[(mhalf+gid)*264 + c0]     = oA0;
                Ssm[(mhalf+gid)*264 + c0 + 1] = oA1;
                Ssm[(mhalf+gid+8)*264 + c0]     = oB0;
                Ssm[(mhalf+gid+8)*264 + c0 + 1] = oB1;
                if (vA) { float2 o; o.x = oA0; o.y = oA1; *(float2*)(s1out + (size_t)grA*256 + c0) = o; }
                if (vB) { float2 o; o.x = oB0; o.y = oB1; *(float2*)(s1out + (size_t)grB*256 + c0) = o; }
            }
        }
        __syncthreads();

        if (tid < 256) {
            #pragma unroll 8
            for (int r = 0; r < 32; r++) colacc += Ssm[r*264 + tid];
        }
        #pragma unroll
        for (int kk = 0; kk < 4; kk++) {
            int kb = kk*8;
            uint32_t a[2][4];
            #pragma unroll
            for (int mf = 0; mf < 2; mf++) {
                int m = msubT + mf*16 + gid;
                a[mf][0] = fbits(Ssm[(kb+tid4)*264   + m  ]);
                a[mf][1] = fbits(Ssm[(kb+tid4)*264   + m+8]);
                a[mf][2] = fbits(Ssm[(kb+tid4+4)*264 + m  ]);
                a[mf][3] = fbits(Ssm[(kb+tid4+4)*264 + m+8]);
            }
            #pragma unroll
            for (int nf = 0; nf < 8; nf++) {
                int c = nsubT + nf*8 + gid;
                uint32_t b0 = fbits(m2s[(kb+tid4)*136 + c]);
                uint32_t b1 = fbits(m2s[(kb+tid4+4)*136 + c]);
                mma_tf32(accT[0][nf], a[0][0], a[0][1], a[0][2], a[0][3], b0, b1);
                mma_tf32(accT[1][nf], a[1][0], a[1][1], a[1][2], a[1][3], b0, b1);
            }
        }
        __syncthreads();
    }

    float* P = g_part + (size_t)chunk * (CC1*DD);
    #pragma unroll
    for (int mf = 0; mf < 2; mf++) {
        int mloc = msubT + mf*16 + gid;
        #pragma unroll
        for (int nf = 0; nf < 8; nf++) {
            int c0 = nsubT + nf*8 + 2*tid4;
            float2 lo; lo.x = accT[mf][nf][0]; lo.y = accT[mf][nf][1];
            float2 hi; hi.x = accT[mf][nf][2]; hi.y = accT[mf][nf][3];
            *(float2*)(P + (size_t)mloc*128 + c0)     = lo;
            *(float2*)(P + (size_t)(mloc+8)*128 + c0) = hi;
        }
    }
    #pragma unroll
    for (int nf = 0; nf < 8; nf++) {
        float cs0 = accT[0][nf][0] + accT[0][nf][2] + accT[1][nf][0] + accT[1][nf][2];
        float cs1 = accT[0][nf][1] + accT[0][nf][3] + accT[1][nf][1] + accT[1][nf][3];
        #pragma unroll
        for (int o = 4; o < 32; o <<= 1) {
            cs0 += __shfl_xor_sync(0xffffffffu, cs0, o);
            cs1 += __shfl_xor_sync(0xffffffffu, cs1, o);
        }
        if (gid == 0) {
            int c0 = nsubT + nf*8 + 2*tid4;
            atomicAdd(&g_sumT[c0],   cs0);
            atomicAdd(&g_sumT[c0+1], cs1);
        }
    }
    if (tid < 256) atomicAdd(&g_colsum[tid], colacc);
}

// ============================ x1 + analytic coarse tail (merged) ============================
__global__ __launch_bounds__(256) void k_x1tail(
    const float* __restrict__ We1, const float* __restrict__ be1,
    const float* __restrict__ We2, const float* __restrict__ be2,
    const float* __restrict__ Wa2, const float* __restrict__ ba2,
    float* __restrict__ out)
{
    int t = threadIdx.x;
    if (blockIdx.x < 128) {
        __shared__ float sT[2][128];
        int rowsel = t >> 7;
        int d = t & 127;
        int k = blockIdx.x*2 + rowsel;
        float s = 0.f;
        #pragma unroll 4
        for (int c = 0; c < SCHUNKS; c++)
            s += g_part[(size_t)c*(CC1*DD) + (size_t)k*128 + d];
        sT[rowsel][d] = s;
        __syncthreads();
        float colk = g_colsum[k];
        float acc = 0.f;
        #pragma unroll 8
        for (int e = 0; e < 128; e++) acc = fmaf(sT[rowsel][e], We1[e*128 + d], acc);
        out[OFF_X1 + k*128 + d] = acc + colk * be1[d];
        return;
    }
    // tail block
    __shared__ float sumT[128];
    __shared__ float meanx1[128];
    __shared__ float meanvec[128];
    __shared__ float s2row[32];
    __shared__ float sc[256];

    if (t < 128) sumT[t] = g_sumT[t];
    sc[t] = g_colsum[t];
    __syncthreads();
    #pragma unroll
    for (int st = 128; st > 0; st >>= 1) {
        if (t < st) sc[t] += sc[t+st];
        __syncthreads();
    }
    float sumcol = sc[0];
    if (t < 128) {
        float s = 0.f;
        for (int e = 0; e < 128; e++) s = fmaf(sumT[e], We1[e*128 + t], s);
        meanx1[t] = (s + sumcol*be1[t]) * (1.0f/256.0f);
    }
    __syncthreads();
    if (t < 128) {
        float s = 0.f;
        for (int e = 0; e < 128; e++) s = fmaf(meanx1[e], We2[e*128 + t], s);
        meanvec[t] = s + be2[t];
    }
    __syncthreads();
    if (t < 32) {
        float s = 0.f;
        for (int d = 0; d < 128; d++) s = fmaf(meanvec[d], Wa2[d*32 + t], s);
        float v = s + ba2[t];
        float mx = v;
        #pragma unroll
        for (int o = 16; o > 0; o >>= 1) mx = fmaxf(mx, __shfl_xor_sync(0xffffffffu, mx, o));
        float ex = __expf(v - mx);
        float sm = ex;
        #pragma unroll
        for (int o = 16; o > 0; o >>= 1) sm += __shfl_xor_sync(0xffffffffu, sm, o);
        s2row[t] = ex / sm;
    }
    __syncthreads();
    for (int i = t; i < 256*32; i += 256) out[OFF_S2 + i] = s2row[i & 31];
    if (t < 32) out[OFF_A1 + t] = 1.0f;
    for (int i = t; i < 32*128; i += 256)
        out[OFF_X2 + i] = 256.0f * s2row[i >> 7] * meanvec[i & 127];
    if (t == 0) {
        float s = 0.f;
        for (int d = 0; d < 128; d++) s += meanvec[d];
        out[OFF_E0] = s * (1.0f/16.0f);
    }
}

// ============================ launch ============================
extern "C" void kernel_launch(void* const* d_in, const int* in_sizes, int n_in,
                              void* d_out, int out_size)
{
    const float* feature = (const float*)d_in[0];
    const int*   eidx    = (const int*)d_in[1];
    const int*   src     = eidx;
    const int*   dst     = eidx + EE;
    const float* Wf   = (const float*)d_in[2];
    const float* bf   = (const float*)d_in[3];
    const float* We1  = (const float*)d_in[4];
    const float* be1  = (const float*)d_in[5];
    const float* Wa1  = (const float*)d_in[6];
    const float* ba1  = (const float*)d_in[7];
    const float* attW1 = (const float*)d_in[8];
    const float* attb1 = (const float*)d_in[9];
    const float* We2  = (const float*)d_in[10];
    const float* be2  = (const float*)d_in[11];
    const float* Wa2  = (const float*)d_in[12];
    const float* ba2  = (const float*)d_in[13];
    float* out = (float*)d_out;

    void *deg_p;
    float *zf_p, *m2_p;
    cudaGetSymbolAddress(&deg_p, g_deg);
    cudaGetSymbolAddress((void**)&zf_p, g_zf);
    cudaGetSymbolAddress((void**)&m2_p, g_m2);

    const int zf_smem = (128*36*2 + 32*136*2) * 4;         // 71680 B
    const int s1atb_smem = S1ATB_SMEM_FLOATS * 4;          // 206336 B
    cudaFuncSetAttribute(k_gemm_zf, cudaFuncAttributeMaxDynamicSharedMemorySize, zf_smem);
    cudaFuncSetAttribute(k_s1atb, cudaFuncAttributeMaxDynamicSharedMemorySize, s1atb_smem);

    cudaStream_t side = g_sr.s;

    // ---- fork: side stream does dense prep ----
    cudaEventRecord(g_sr.fork, 0);
    cudaStreamWaitEvent(side, g_sr.fork, 0);
    k_gemm_zf<<<(NN+127)/128, 256, zf_smem, side>>>(feature, Wf, bf, zf_p);
    k_fold<<<129, 256, 0, side>>>(We1, be1, Wa1, ba1, attW1);  // also zeroes colsum/sumT
    cudaEventRecord(g_sr.join, side);

    // ---- main stream: graph build ----
    cudaMemsetAsync(deg_p, 0, NN*sizeof(int));
    k_count<<<(EE + 255)/256, 256>>>(dst);
    k_scanall<<<SCANB, 1024>>>();
    k_fill<<<(EE + 255)/256, 256>>>(src, dst);

    // ---- join, then serial chain ----
    cudaStreamWaitEvent(0, g_sr.join, 0);

    // embed3 = x = normalize(segmean(zf))
    k_segmean<true,false><<<(NN+15)/16, 256>>>(zf_p, out + OFF_E3);
    // m2 = segmean(x) + fused a_src/a_dst
    k_segmean<false,true><<<(NN+15)/16, 256>>>(out + OFF_E3, m2_p);
    // GAT aggregation on 128-wide m2
    k_gatagg<<<(NN+15)/16, 256>>>(attb1);
    // FUSED: s1 softmax GEMM + T partials + sumT/colsum (148 blocks, 1/SM)
    k_s1atb<<<SCHUNKS, 512, s1atb_smem>>>(out + OFF_S1);
    // x1 (128 blocks) + analytic tail (block 128)
    k_x1tail<<<129, 256>>>(We1, be1, We2, be2, Wa2, ba2, out);
}